// round 2
// baseline (speedup 1.0000x reference)
#include <cuda_runtime.h>

#define NB 2
#define P3 884736   // 96^3

// ---------------- scratch (static device globals; no allocation) ----------------
__device__ float g_a1[NB*32*48*48*48];   // 28.3 MB
__device__ float g_a2[NB*64*24*24*24];   // 7.1 MB
__device__ float g_a3[NB*128*12*12*12];
__device__ float g_a4[NB*256*6*6*6];
__device__ float g_a5[NB*512*3*3*3];
__device__ float g_a6[NB*512];
__device__ float g_z [NB*128];
__device__ float g_knots[NB*3*512];
__device__ float g_feats[NB*3*512*32];

// ---------------- direct conv: block = (oc, spatial tile, batch) ----------------
// Consecutive blocks vary oc fastest -> co-resident blocks reuse the same input
// patch through L1; weights are warp-uniform __ldg broadcasts.
template<int CIN, int COUT, int IS, int OS>
__global__ __launch_bounds__(256) void conv_direct(
    const float* __restrict__ in, const float* __restrict__ w,
    const float* __restrict__ bias, float* __restrict__ out)
{
    const int SP = OS*OS*OS;
    int oc = blockIdx.x;
    int b  = blockIdx.z;
    int p  = blockIdx.y*blockDim.x + threadIdx.x;
    if (p >= SP) return;
    int x = p % OS, y = (p/OS)%OS, z = p/(OS*OS);
    int z0 = 2*z-1, y0 = 2*y-1, x0 = 2*x-1;
    float a0=0.f, a1=0.f, a2=0.f, a3=0.f;   // split accumulators (break RAW chain)
    const float* wb = w  + (size_t)oc*CIN*64;
    const float* ib = in + (size_t)b*CIN*IS*IS*IS;
    for (int ic = 0; ic < CIN; ic++) {
        const float* ip = ib + (size_t)ic*IS*IS*IS;
        const float* wp = wb + ic*64;
        #pragma unroll
        for (int kz=0; kz<4; kz++){
            int iz = z0+kz; if (iz < 0 || iz >= IS) continue;
            #pragma unroll
            for (int ky=0; ky<4; ky++){
                int iy = y0+ky; if (iy < 0 || iy >= IS) continue;
                const float* row = ip + ((size_t)iz*IS + iy)*IS;
                #pragma unroll
                for (int kx=0; kx<4; kx++){
                    int ix = x0+kx; if (ix < 0 || ix >= IS) continue;
                    float v = row[ix] * __ldg(wp + ((kz*4+ky)*4+kx));
                    if      (kx==0) a0 += v;
                    else if (kx==1) a1 += v;
                    else if (kx==2) a2 += v;
                    else            a3 += v;
                }
            }
        }
    }
    float acc = ((a0+a1)+(a2+a3)) + bias[oc];
    out[((size_t)b*COUT + oc)*SP + p] = fmaxf(acc, 0.f);
}

// ------------- reduction conv for tiny-spatial deep layers (4,5,6) -------------
// Block per output element; 64 threads = 64 taps; each valid tap loops over CIN.
template<int CIN, int COUT, int IS, int OS>
__global__ __launch_bounds__(64) void conv_reduce(
    const float* __restrict__ in, const float* __restrict__ w,
    const float* __restrict__ bias, float* __restrict__ out)
{
    const int SP = OS*OS*OS;
    int n = blockIdx.x;
    int x = n % OS; int t = n/OS;
    int y = t % OS; t /= OS;
    int z = t % OS; t /= OS;
    int oc = t % COUT; int b = t / COUT;
    int tid = threadIdx.x;                  // tap index 0..63
    int kz = tid>>4, ky = (tid>>2)&3, kx = tid&3;
    int iz = 2*z-1+kz, iy = 2*y-1+ky, ix = 2*x-1+kx;
    bool valid = (iz>=0)&&(iz<IS)&&(iy>=0)&&(iy<IS)&&(ix>=0)&&(ix<IS);
    float acc = 0.f;
    if (valid) {
        const float* ip = in + (size_t)b*CIN*IS*IS*IS + ((size_t)iz*IS + iy)*IS + ix;
        const float* wp = w  + (size_t)oc*CIN*64 + tid;
        for (int ic = 0; ic < CIN; ic++)
            acc += ip[(size_t)ic*IS*IS*IS] * wp[(size_t)ic*64];
    }
    #pragma unroll
    for (int o = 16; o > 0; o >>= 1) acc += __shfl_xor_sync(0xffffffffu, acc, o);
    __shared__ float s[2];
    if ((tid & 31) == 0) s[tid>>5] = acc;
    __syncthreads();
    if (tid == 0)
        out[n] = fmaxf(s[0] + s[1] + bias[oc], 0.f);
}

// ---------------- VAE head: mu/logvar/z (tiny) ----------------
__global__ void stats_kernel(const float* __restrict__ a6, const float* __restrict__ fc_w,
                             const float* __restrict__ fc_b, const float* __restrict__ eps,
                             float* __restrict__ zout, float* __restrict__ out_mu,
                             float* __restrict__ out_lv)
{
    int t = threadIdx.x;
    if (t >= 256) return;
    int b = t >> 7, j = t & 127;
    const float* a = a6 + b*512;
    float mu = fc_b[j], lv = fc_b[128+j];
    for (int k = 0; k < 512; k++) {
        float av = a[k];
        mu += av * fc_w[k*256 + j];
        lv += av * fc_w[k*256 + 128 + j];
    }
    float zz = mu + eps[b*128+j] * expf(0.5f*lv);
    zout[b*128+j] = zz;
    out_mu[b*128+j] = mu;
    out_lv[b*128+j] = lv;
}

// ---------------- deltas -> softmax -> cumsum knots (6 blocks) ----------------
__global__ void knots_kernel(const float* __restrict__ z, const float* __restrict__ dl_w,
                             const float* __restrict__ dl_b, float* __restrict__ knots)
{
    int b = blockIdx.x / 3, a = blockIdx.x % 3;
    __shared__ float sz[128];
    __shared__ float sd[512];
    __shared__ float red[512];
    int tid = threadIdx.x;
    if (tid < 128) sz[tid] = z[b*128 + tid];
    __syncthreads();
    float d = -1e30f;
    if (tid < 511) {
        int col = a*511 + tid;
        d = dl_b[col];
        for (int k = 0; k < 128; k++) d += sz[k] * dl_w[k*1533 + col];
    }
    sd[tid] = d; red[tid] = d;
    __syncthreads();
    for (int o = 256; o > 0; o >>= 1) { if (tid < o) red[tid] = fmaxf(red[tid], red[tid+o]); __syncthreads(); }
    float m = red[0];
    __syncthreads();
    float e = (tid < 511) ? expf(sd[tid] - m) : 0.f;
    red[tid] = e;
    __syncthreads();
    for (int o = 256; o > 0; o >>= 1) { if (tid < o) red[tid] += red[tid+o]; __syncthreads(); }
    float S = red[0];
    __syncthreads();
    if (tid < 511) sd[tid] = e / S;          // softmax "rel" like reference
    __syncthreads();
    if (tid == 0) {
        float* kp = knots + ((size_t)b*3 + a)*512;
        float run = 0.f;
        kp[0] = 0.f;
        for (int i = 0; i < 511; i++) { run += sd[i]; kp[i+1] = run; }
    }
}

// ---------------- feats = relu(z @ fl_w + fl_b) ----------------
__global__ void feats_kernel(const float* __restrict__ z, const float* __restrict__ fl_w,
                             const float* __restrict__ fl_b, float* __restrict__ feats)
{
    int idx = blockIdx.x*blockDim.x + threadIdx.x;
    if (idx >= NB*49152) return;
    int b = idx / 49152, c = idx % 49152;
    float acc = fl_b[c];
    const float* zp = z + b*128;
    for (int k = 0; k < 128; k++)
        acc += __ldg(zp + k) * fl_w[(size_t)k*49152 + c];
    feats[idx] = fmaxf(acc, 0.f);
}

// ---------------- fused triline query + decoder MLP ----------------
__global__ __launch_bounds__(256) void decode_kernel(
    const float* __restrict__ coords, const float* __restrict__ knots,
    const float* __restrict__ feats, const float* __restrict__ w1,
    const float* __restrict__ b1, const float* __restrict__ w2,
    const float* __restrict__ b2, float* __restrict__ out)
{
    __shared__ float skn[1536];     // knots for this batch, 3 axes
    __shared__ float sw1[2048];     // dec_w1 transposed [j][d]
    __shared__ float sb1[64];
    __shared__ float sw2[64];
    int tid = threadIdx.x;
    int g = blockIdx.x*256 + tid;
    int b = g / P3;                 // uniform per block (P3 % 256 == 0)
    int p = g - b*P3;
    for (int i = tid; i < 1536; i += 256) skn[i] = knots[b*1536 + i];
    for (int i = tid; i < 2048; i += 256) { int d = i>>6, j = i&63; sw1[j*32 + d] = w1[i]; }
    if (tid < 64) { sb1[tid] = b1[tid]; sw2[tid] = w2[tid]; }
    __syncthreads();

    float4 f4[8];
    #pragma unroll
    for (int a = 0; a < 3; a++) {
        float u = coords[(size_t)p*3 + a] + 0.5f;
        const float* kn = skn + a*512;
        int lo = 0, hi = 512;
        #pragma unroll
        for (int it = 0; it < 9; it++) {
            int mid = (lo + hi) >> 1;
            bool le = (kn[mid] <= u);
            lo = le ? (mid + 1) : lo;
            hi = le ? hi : mid;
        }
        int idx = lo - 1;
        idx = (idx < 0) ? 0 : ((idx > 510) ? 510 : idx);
        float t0 = kn[idx], t1 = kn[idx+1];
        float wgt = (u - t0) / (t1 - t0 + 1e-8f);
        wgt = fminf(fmaxf(wgt, 0.f), 1.f);
        float om = 1.f - wgt;
        const float4* fr = (const float4*)(feats + (((size_t)b*3 + a)*512 + idx)*32);
        #pragma unroll
        for (int q = 0; q < 8; q++) {
            float4 r0 = fr[q], r1 = fr[q+8];   // rows idx and idx+1 (contiguous)
            float vx = r0.x*om + r1.x*wgt;
            float vy = r0.y*om + r1.y*wgt;
            float vz = r0.z*om + r1.z*wgt;
            float vw = r0.w*om + r1.w*wgt;
            if (a == 0) { f4[q] = make_float4(vx, vy, vz, vw); }
            else        { f4[q].x *= vx; f4[q].y *= vy; f4[q].z *= vz; f4[q].w *= vw; }
        }
    }

    float logit = __ldg(b2);
    const float4* w1v = (const float4*)sw1;
    #pragma unroll 8
    for (int j = 0; j < 64; j++) {
        float h0=0.f, h1=0.f, h2=0.f, h3=0.f;
        #pragma unroll
        for (int q = 0; q < 8; q++) {
            float4 wv = w1v[j*8 + q];
            h0 += f4[q].x*wv.x; h1 += f4[q].y*wv.y;
            h2 += f4[q].z*wv.z; h3 += f4[q].w*wv.w;
        }
        float h = sb1[j] + ((h0+h1)+(h2+h3));
        logit += fmaxf(h, 0.f) * sw2[j];
    }
    out[g] = logit;
}

// ---------------- launch ----------------
extern "C" void kernel_launch(void* const* d_in, const int* in_sizes, int n_in,
                              void* d_out, int out_size)
{
    const float* occ    = (const float*)d_in[0];
    const float* eps    = (const float*)d_in[1];
    const float* coords = (const float*)d_in[2];
    const float* cw0=(const float*)d_in[3];  const float* cb0=(const float*)d_in[4];
    const float* cw1=(const float*)d_in[5];  const float* cb1=(const float*)d_in[6];
    const float* cw2=(const float*)d_in[7];  const float* cb2=(const float*)d_in[8];
    const float* cw3=(const float*)d_in[9];  const float* cb3=(const float*)d_in[10];
    const float* cw4=(const float*)d_in[11]; const float* cb4=(const float*)d_in[12];
    const float* cw5=(const float*)d_in[13]; const float* cb5=(const float*)d_in[14];
    const float* fc_w=(const float*)d_in[15]; const float* fc_b=(const float*)d_in[16];
    const float* dl_w=(const float*)d_in[17]; const float* dl_b=(const float*)d_in[18];
    const float* fl_w=(const float*)d_in[19]; const float* fl_b=(const float*)d_in[20];
    const float* dw1=(const float*)d_in[21]; const float* db1=(const float*)d_in[22];
    const float* dw2=(const float*)d_in[23]; const float* db2=(const float*)d_in[24];
    float* out = (float*)d_out;

    float *a1,*a2,*a3,*a4,*a5,*a6,*zp,*kn,*ft;
    cudaGetSymbolAddress((void**)&a1, g_a1);
    cudaGetSymbolAddress((void**)&a2, g_a2);
    cudaGetSymbolAddress((void**)&a3, g_a3);
    cudaGetSymbolAddress((void**)&a4, g_a4);
    cudaGetSymbolAddress((void**)&a5, g_a5);
    cudaGetSymbolAddress((void**)&a6, g_a6);
    cudaGetSymbolAddress((void**)&zp, g_z);
    cudaGetSymbolAddress((void**)&kn, g_knots);
    cudaGetSymbolAddress((void**)&ft, g_feats);

    // encoder
    conv_direct<1,  32, 96, 48><<<dim3(32,  48*48*48/256, NB), 256>>>(occ, cw0, cb0, a1);
    conv_direct<32, 64, 48, 24><<<dim3(64,  24*24*24/256, NB), 256>>>(a1,  cw1, cb1, a2);
    conv_direct<64,128, 24, 12><<<dim3(128, (12*12*12+255)/256, NB), 256>>>(a2, cw2, cb2, a3);
    conv_reduce<128,256,12, 6><<<NB*256*216, 64>>>(a3, cw3, cb3, a4);
    conv_reduce<256,512, 6, 3><<<NB*512*27,  64>>>(a4, cw4, cb4, a5);
    conv_reduce<512,512, 3, 1><<<NB*512,     64>>>(a5, cw5, cb5, a6);

    // VAE head + latent decoders (outputs mu/logvar straight into d_out)
    stats_kernel<<<1, 256>>>(a6, fc_w, fc_b, eps, zp, out + NB*P3, out + NB*P3 + NB*128);
    knots_kernel<<<6, 512>>>(zp, dl_w, dl_b, kn);
    feats_kernel<<<(NB*49152 + 127)/128, 128>>>(zp, fl_w, fl_b, ft);

    // fused triline query + MLP decoder -> pred_occ
    decode_kernel<<<NB*P3/256, 256>>>(coords, kn, ft, dw1, db1, dw2, db2, out);
}

// round 4
// speedup vs baseline: 1.8373x; 1.8373x over previous
#include <cuda_runtime.h>

#define NB 2
#define P3 884736   // 96^3

// ---------------- scratch (static device globals; no allocation) ----------------
__device__ float g_a1[NB*32*48*48*48];
__device__ float g_a2[NB*64*24*24*24];
__device__ float g_a3[NB*128*12*12*12];
__device__ float g_a4[NB*256*6*6*6];
__device__ float g_a5[NB*512*3*3*3];
__device__ float g_a6[NB*512];
__device__ float g_z [NB*128];
__device__ float g_knots[NB*3*512];
__device__ float g_feats[NB*3*512*32];
__device__ float g_colA[8192*432];      // max im2col (conv3); conv4 fits too
__device__ float g_part[8*432*256];     // max split-K partial (conv3); conv4 fits

// =====================================================================
// Tiled direct conv with per-thread oc register tiling (conv0/1/2).
// =====================================================================
template<int CIN,int COUT,int IS,int OS,int OCB,int OCT,int ICC,int TZ,int TY,int TX>
__global__ __launch_bounds__(TZ*TY*TX*(OCB/OCT)) void conv_tile(
    const float* __restrict__ in, const float* __restrict__ w,
    const float* __restrict__ bias, float* __restrict__ out)
{
    constexpr int NPOS   = TZ*TY*TX;
    constexpr int GROUPS = OCB/OCT;
    constexpr int NTH    = NPOS*GROUPS;
    constexpr int PX = 2*TX+2, PY = 2*TY+2, PZ = 2*TZ+2;
    constexpr int PATCH = ICC*PZ*PY*PX;
    constexpr int WSTR  = OCB+4;
    constexpr int SP = OS*OS*OS;

    __shared__ float patch[PATCH];
    __shared__ float wsm[ICC*64*WSTR];

    const int oc0 = blockIdx.x * OCB;
    const int b   = blockIdx.z;
    int t = blockIdx.y;
    constexpr int NTX = OS/TX, NTY = OS/TY;
    const int txi = t % NTX; t /= NTX;
    const int tyi = t % NTY; t /= NTY;
    const int tzi = t;
    const int ox0 = txi*TX, oy0 = tyi*TY, oz0 = tzi*TZ;
    const int gx0 = 2*ox0-1, gy0 = 2*oy0-1, gz0 = 2*oz0-1;

    const int tid = threadIdx.x;
    const int g   = tid % GROUPS;
    const int pos = tid / GROUPS;
    const int lx = pos % TX;
    const int ly = (pos/TX) % TY;
    const int lz = pos/(TX*TY);

    float acc[OCT];
    #pragma unroll
    for (int j = 0; j < OCT; j++) acc[j] = 0.f;

    for (int ic0 = 0; ic0 < CIN; ic0 += ICC) {
        for (int i = tid; i < PATCH; i += NTH) {
            int px = i % PX; int r = i/PX;
            int py = r % PY; r /= PY;
            int pz = r % PZ; int ic = r / PZ;
            int ix = gx0+px, iy = gy0+py, iz = gz0+pz;
            float v = 0.f;
            if (ix>=0 && ix<IS && iy>=0 && iy<IS && iz>=0 && iz<IS)
                v = in[(((size_t)(b*CIN + ic0+ic)*IS + iz)*IS + iy)*IS + ix];
            patch[i] = v;
        }
        for (int i = tid; i < OCB*ICC*64; i += NTH) {
            int r  = i % (ICC*64);
            int oc = i / (ICC*64);
            wsm[r*WSTR + oc] = w[((size_t)(oc0+oc)*CIN + ic0)*64 + r];
        }
        __syncthreads();
        for (int ic = 0; ic < ICC; ic++) {
            for (int kz = 0; kz < 4; kz++) {
                for (int ky = 0; ky < 4; ky++) {
                    const float* prow = &patch[((ic*PZ + 2*lz+kz)*PY + 2*ly+ky)*PX + 2*lx];
                    const float* wrow = &wsm[(ic*64 + kz*16 + ky*4)*WSTR + g*OCT];
                    #pragma unroll
                    for (int kx = 0; kx < 4; kx++) {
                        float v = prow[kx];
                        const float4* w4p = (const float4*)(wrow + kx*WSTR);
                        #pragma unroll
                        for (int j = 0; j < OCT/4; j++) {
                            float4 w4 = w4p[j];
                            acc[4*j+0] += v*w4.x;
                            acc[4*j+1] += v*w4.y;
                            acc[4*j+2] += v*w4.z;
                            acc[4*j+3] += v*w4.w;
                        }
                    }
                }
            }
        }
        __syncthreads();
    }
    const int gz = oz0+lz, gy = oy0+ly, gx = ox0+lx;
    const int spi = (gz*OS + gy)*OS + gx;
    #pragma unroll
    for (int j = 0; j < OCT; j++) {
        int oc = oc0 + g*OCT + j;
        out[((size_t)(b*COUT + oc))*SP + spi] = fmaxf(acc[j] + bias[oc], 0.f);
    }
}

// =====================================================================
// im2col: A[k][m], k = ic*64+tap, m = b*OS^3 + spatial
// =====================================================================
template<int CIN,int IS,int OS>
__global__ void im2col_kernel(const float* __restrict__ in, float* __restrict__ A)
{
    constexpr int SP = OS*OS*OS;
    constexpr int M  = NB*SP;
    constexpr int K  = CIN*64;
    int idx = blockIdx.x*256 + threadIdx.x;
    if (idx >= K*M) return;
    int m = idx % M;
    int k = idx / M;
    int sp = m % SP, b = m / SP;
    int x = sp % OS, y = (sp/OS)%OS, z = sp/(OS*OS);
    int tap = k & 63, ic = k >> 6;
    int kz = tap>>4, ky = (tap>>2)&3, kx = tap&3;
    int iz = 2*z-1+kz, iy = 2*y-1+ky, ix = 2*x-1+kx;
    float v = 0.f;
    if (ix>=0 && ix<IS && iy>=0 && iy<IS && iz>=0 && iz<IS)
        v = in[(((size_t)(b*CIN+ic)*IS + iz)*IS + iy)*IS + ix];
    A[idx] = v;
}

// =====================================================================
// Split-K SGEMM partial
// =====================================================================
template<int MT,int NT,int KC,int KS>
__global__ __launch_bounds__(256) void gemm_partial(
    const float* __restrict__ A, const float* __restrict__ W,
    float* __restrict__ part, int M, int N, int K)
{
    constexpr int WS = NT+4;
    __shared__ float As[KC*MT];
    __shared__ float Ws[KC*WS];
    const int m0 = blockIdx.x*MT, n0 = blockIdx.y*NT, s = blockIdx.z;
    const int k0 = s*KS;
    const int tid = threadIdx.x;
    const int tn = tid & 15, tm = tid >> 4;

    float acc[4][4];
    #pragma unroll
    for (int i=0;i<4;i++)
        #pragma unroll
        for (int j=0;j<4;j++) acc[i][j]=0.f;

    for (int kc = 0; kc < KS; kc += KC) {
        #pragma unroll
        for (int i = 0; i < (KC*MT)/256; i++) {
            int idx = tid + i*256;
            int m = idx % MT, kk = idx / MT;
            int gm = m0 + m;
            As[kk*MT + m] = (gm < M) ? A[(size_t)(k0+kc+kk)*M + gm] : 0.f;
        }
        #pragma unroll
        for (int i = 0; i < (KC*NT)/256; i++) {
            int idx = tid + i*256;
            int kk = idx % KC, n = idx / KC;
            Ws[kk*WS + n] = W[(size_t)(n0+n)*K + k0+kc+kk];
        }
        __syncthreads();
        #pragma unroll 8
        for (int kk = 0; kk < KC; kk++) {
            float4 a4 = *(const float4*)&As[kk*MT + tm*4];
            float4 w4 = *(const float4*)&Ws[kk*WS + tn*4];
            acc[0][0]+=a4.x*w4.x; acc[0][1]+=a4.x*w4.y; acc[0][2]+=a4.x*w4.z; acc[0][3]+=a4.x*w4.w;
            acc[1][0]+=a4.y*w4.x; acc[1][1]+=a4.y*w4.y; acc[1][2]+=a4.y*w4.z; acc[1][3]+=a4.y*w4.w;
            acc[2][0]+=a4.z*w4.x; acc[2][1]+=a4.z*w4.y; acc[2][2]+=a4.z*w4.z; acc[2][3]+=a4.z*w4.w;
            acc[3][0]+=a4.w*w4.x; acc[3][1]+=a4.w*w4.y; acc[3][2]+=a4.w*w4.z; acc[3][3]+=a4.w*w4.w;
        }
        __syncthreads();
    }
    #pragma unroll
    for (int i = 0; i < 4; i++) {
        int gm = m0 + tm*4 + i;
        if (gm < M) {
            float4 v = make_float4(acc[i][0],acc[i][1],acc[i][2],acc[i][3]);
            *(float4*)&part[((size_t)s*M + gm)*N + n0 + tn*4] = v;
        }
    }
}

// ---- fixed-order split-K reduce + bias + relu, writes [b][oc][sp] ----
template<int COUT,int OS,int S>
__global__ void reduce_bias_relu(const float* __restrict__ part, const float* __restrict__ bias,
                                 float* __restrict__ out)
{
    constexpr int SP = OS*OS*OS;
    constexpr int M  = NB*SP;
    int idx = blockIdx.x*256 + threadIdx.x;
    if (idx >= M*COUT) return;
    int n = idx % COUT, m = idx / COUT;
    float acc = bias[n];
    #pragma unroll
    for (int s = 0; s < S; s++) acc += part[((size_t)s*M + m)*COUT + n];
    int b = m / SP, sp = m % SP;
    out[((size_t)(b*COUT + n))*SP + sp] = fmaxf(acc, 0.f);
}

// =====================================================================
// conv5 (512->512, 3^3 -> 1): weight-streaming GEMV, both batches.
// =====================================================================
__global__ __launch_bounds__(256) void conv5_kernel(
    const float* __restrict__ a5, const float* __restrict__ w,
    const float* __restrict__ bias, float* __restrict__ a6)
{
    const int oc = blockIdx.x;
    const int tid = threadIdx.x;
    float acc0 = 0.f, acc1 = 0.f;
    const float4* wp = (const float4*)(w + (size_t)oc*32768);
    #pragma unroll 4
    for (int i = 0; i < 32; i++) {
        int q = i*256 + tid;
        float4 w4 = __ldg(wp + q);
        int k4 = q*4;
        int ic  = k4 >> 6;
        int tap = k4 & 63;
        int kz = tap >> 4, ky = (tap>>2)&3;
        if (kz >= 1 && ky >= 1) {
            int off = ic*27 + ((kz-1)*3 + (ky-1))*3;
            const float* p0 = a5 + off;
            const float* p1 = a5 + 512*27 + off;
            acc0 += w4.y*p0[0] + w4.z*p0[1] + w4.w*p0[2];
            acc1 += w4.y*p1[0] + w4.z*p1[1] + w4.w*p1[2];
        }
    }
    #pragma unroll
    for (int o = 16; o > 0; o >>= 1) {
        acc0 += __shfl_xor_sync(0xffffffffu, acc0, o);
        acc1 += __shfl_xor_sync(0xffffffffu, acc1, o);
    }
    __shared__ float s0[8], s1[8];
    if ((tid & 31) == 0) { s0[tid>>5] = acc0; s1[tid>>5] = acc1; }
    __syncthreads();
    if (tid == 0) {
        float t0 = 0.f, t1 = 0.f;
        for (int i = 0; i < 8; i++) { t0 += s0[i]; t1 += s1[i]; }
        a6[oc]       = fmaxf(t0 + bias[oc], 0.f);
        a6[512 + oc] = fmaxf(t1 + bias[oc], 0.f);
    }
}

// ---------------- VAE head: mu/logvar/z ----------------
__global__ void stats_kernel(const float* __restrict__ a6, const float* __restrict__ fc_w,
                             const float* __restrict__ fc_b, const float* __restrict__ eps,
                             float* __restrict__ zout, float* __restrict__ out_mu,
                             float* __restrict__ out_lv)
{
    int t = threadIdx.x;
    if (t >= 256) return;
    int b = t >> 7, j = t & 127;
    const float* a = a6 + b*512;
    float mu = fc_b[j], lv = fc_b[128+j];
    for (int k = 0; k < 512; k++) {
        float av = a[k];
        mu += av * fc_w[k*256 + j];
        lv += av * fc_w[k*256 + 128 + j];
    }
    float zz = mu + eps[b*128+j] * expf(0.5f*lv);
    zout[b*128+j] = zz;
    out_mu[b*128+j] = mu;
    out_lv[b*128+j] = lv;
}

// ---------------- deltas -> softmax -> cumsum knots ----------------
__global__ void knots_kernel(const float* __restrict__ z, const float* __restrict__ dl_w,
                             const float* __restrict__ dl_b, float* __restrict__ knots)
{
    int b = blockIdx.x / 3, a = blockIdx.x % 3;
    __shared__ float sz[128];
    __shared__ float sd[512];
    __shared__ float red[512];
    int tid = threadIdx.x;
    if (tid < 128) sz[tid] = z[b*128 + tid];
    __syncthreads();
    float d = -1e30f;
    if (tid < 511) {
        int col = a*511 + tid;
        d = dl_b[col];
        for (int k = 0; k < 128; k++) d += sz[k] * dl_w[k*1533 + col];
    }
    sd[tid] = d; red[tid] = d;
    __syncthreads();
    for (int o = 256; o > 0; o >>= 1) { if (tid < o) red[tid] = fmaxf(red[tid], red[tid+o]); __syncthreads(); }
    float m = red[0];
    __syncthreads();
    float e = (tid < 511) ? expf(sd[tid] - m) : 0.f;
    red[tid] = e;
    __syncthreads();
    for (int o = 256; o > 0; o >>= 1) { if (tid < o) red[tid] += red[tid+o]; __syncthreads(); }
    float S = red[0];
    __syncthreads();
    if (tid < 511) sd[tid] = e / S;
    __syncthreads();
    if (tid == 0) {
        float* kp = knots + ((size_t)b*3 + a)*512;
        float run = 0.f;
        kp[0] = 0.f;
        for (int i = 0; i < 511; i++) { run += sd[i]; kp[i+1] = run; }
    }
}

// ---------------- feats = relu(z @ fl_w + fl_b) ----------------
__global__ void feats_kernel(const float* __restrict__ z, const float* __restrict__ fl_w,
                             const float* __restrict__ fl_b, float* __restrict__ feats)
{
    int idx = blockIdx.x*blockDim.x + threadIdx.x;
    if (idx >= NB*49152) return;
    int b = idx / 49152, c = idx % 49152;
    float acc = fl_b[c];
    const float* zp = z + b*128;
    for (int k = 0; k < 128; k++)
        acc += __ldg(zp + k) * fl_w[(size_t)k*49152 + c];
    feats[idx] = fmaxf(acc, 0.f);
}

// ---------------- fused triline query + decoder MLP ----------------
__global__ __launch_bounds__(256) void decode_kernel(
    const float* __restrict__ coords, const float* __restrict__ knots,
    const float* __restrict__ feats, const float* __restrict__ w1,
    const float* __restrict__ b1, const float* __restrict__ w2,
    const float* __restrict__ b2, float* __restrict__ out)
{
    __shared__ float skn[1536];
    __shared__ float sw1[2048];
    __shared__ float sb1[64];
    __shared__ float sw2[64];
    int tid = threadIdx.x;
    int g = blockIdx.x*256 + tid;
    int b = g / P3;
    int p = g - b*P3;
    for (int i = tid; i < 1536; i += 256) skn[i] = knots[b*1536 + i];
    for (int i = tid; i < 2048; i += 256) { int d = i>>6, j = i&63; sw1[j*32 + d] = w1[i]; }
    if (tid < 64) { sb1[tid] = b1[tid]; sw2[tid] = w2[tid]; }
    __syncthreads();

    float4 f4[8];
    #pragma unroll
    for (int a = 0; a < 3; a++) {
        float u = coords[(size_t)p*3 + a] + 0.5f;
        const float* kn = skn + a*512;
        int lo = 0, hi = 512;
        #pragma unroll
        for (int it = 0; it < 9; it++) {
            int mid = (lo + hi) >> 1;
            bool le = (kn[mid] <= u);
            lo = le ? (mid + 1) : lo;
            hi = le ? hi : mid;
        }
        int idx = lo - 1;
        idx = (idx < 0) ? 0 : ((idx > 510) ? 510 : idx);
        float t0 = kn[idx], t1 = kn[idx+1];
        float wgt = (u - t0) / (t1 - t0 + 1e-8f);
        wgt = fminf(fmaxf(wgt, 0.f), 1.f);
        float om = 1.f - wgt;
        const float4* fr = (const float4*)(feats + (((size_t)b*3 + a)*512 + idx)*32);
        #pragma unroll
        for (int q = 0; q < 8; q++) {
            float4 r0 = fr[q], r1 = fr[q+8];
            float vx = r0.x*om + r1.x*wgt;
            float vy = r0.y*om + r1.y*wgt;
            float vz = r0.z*om + r1.z*wgt;
            float vw = r0.w*om + r1.w*wgt;
            if (a == 0) { f4[q] = make_float4(vx, vy, vz, vw); }
            else        { f4[q].x *= vx; f4[q].y *= vy; f4[q].z *= vz; f4[q].w *= vw; }
        }
    }

    float logit = __ldg(b2);
    const float4* w1v = (const float4*)sw1;
    #pragma unroll 8
    for (int j = 0; j < 64; j++) {
        float h0=0.f, h1=0.f, h2=0.f, h3=0.f;
        #pragma unroll
        for (int q = 0; q < 8; q++) {
            float4 wv = w1v[j*8 + q];
            h0 += f4[q].x*wv.x; h1 += f4[q].y*wv.y;
            h2 += f4[q].z*wv.z; h3 += f4[q].w*wv.w;
        }
        float h = sb1[j] + ((h0+h1)+(h2+h3));
        logit += fmaxf(h, 0.f) * sw2[j];
    }
    out[g] = logit;
}

// ---------------- launch ----------------
extern "C" void kernel_launch(void* const* d_in, const int* in_sizes, int n_in,
                              void* d_out, int out_size)
{
    const float* occ    = (const float*)d_in[0];
    const float* eps    = (const float*)d_in[1];
    const float* coords = (const float*)d_in[2];
    const float* cw0=(const float*)d_in[3];  const float* cb0=(const float*)d_in[4];
    const float* cw1=(const float*)d_in[5];  const float* cb1=(const float*)d_in[6];
    const float* cw2=(const float*)d_in[7];  const float* cb2=(const float*)d_in[8];
    const float* cw3=(const float*)d_in[9];  const float* cb3=(const float*)d_in[10];
    const float* cw4=(const float*)d_in[11]; const float* cb4=(const float*)d_in[12];
    const float* cw5=(const float*)d_in[13]; const float* cb5=(const float*)d_in[14];
    const float* fc_w=(const float*)d_in[15]; const float* fc_b=(const float*)d_in[16];
    const float* dl_w=(const float*)d_in[17]; const float* dl_b=(const float*)d_in[18];
    const float* fl_w=(const float*)d_in[19]; const float* fl_b=(const float*)d_in[20];
    const float* dw1=(const float*)d_in[21]; const float* db1=(const float*)d_in[22];
    const float* dw2=(const float*)d_in[23]; const float* db2=(const float*)d_in[24];
    float* out = (float*)d_out;

    float *a1,*a2,*a3,*a4,*a5,*a6,*zp,*kn,*ft,*colA,*part;
    cudaGetSymbolAddress((void**)&a1, g_a1);
    cudaGetSymbolAddress((void**)&a2, g_a2);
    cudaGetSymbolAddress((void**)&a3, g_a3);
    cudaGetSymbolAddress((void**)&a4, g_a4);
    cudaGetSymbolAddress((void**)&a5, g_a5);
    cudaGetSymbolAddress((void**)&a6, g_a6);
    cudaGetSymbolAddress((void**)&zp, g_z);
    cudaGetSymbolAddress((void**)&kn, g_knots);
    cudaGetSymbolAddress((void**)&ft, g_feats);
    cudaGetSymbolAddress((void**)&colA, g_colA);
    cudaGetSymbolAddress((void**)&part, g_part);

    // ---- encoder: conv0/1/2 tiled-direct ----
    conv_tile<1,  32, 96, 48, 32, 32, 1, 4, 8, 8><<<dim3(1, 432, NB), 256>>>(occ, cw0, cb0, a1);
    conv_tile<32, 64, 48, 24, 64, 16, 2, 4, 4, 4><<<dim3(1, 216, NB), 256>>>(a1,  cw1, cb1, a2);
    conv_tile<64,128, 24, 12, 32,  8, 2, 4, 4, 4><<<dim3(4,  27, NB), 256>>>(a2,  cw2, cb2, a3);

    // ---- conv3: im2col + split-K GEMM (M=432, N=256, K=8192, S=8) ----
    im2col_kernel<128,12,6><<<(8192*432 + 255)/256, 256>>>(a3, colA);
    gemm_partial<64,64,32,1024><<<dim3(7,4,8), 256>>>(colA, cw3, part, 432, 256, 8192);
    reduce_bias_relu<256,6,8><<<(432*256 + 255)/256, 256>>>(part, cb3, a4);

    // ---- conv4: im2col + split-K GEMM (M=54, N=512, K=16384, S=16) ----
    im2col_kernel<256,6,3><<<(16384*54 + 255)/256, 256>>>(a4, colA);
    gemm_partial<64,64,32,1024><<<dim3(1,8,16), 256>>>(colA, cw4, part, 54, 512, 16384);
    reduce_bias_relu<512,3,16><<<(54*512 + 255)/256, 256>>>(part, cb4, a5);

    // ---- conv5: weight-streaming GEMV ----
    conv5_kernel<<<512, 256>>>(a5, cw5, cb5, a6);

    // ---- VAE head + latent decoders ----
    stats_kernel<<<1, 256>>>(a6, fc_w, fc_b, eps, zp, out + NB*P3, out + NB*P3 + NB*128);
    knots_kernel<<<6, 512>>>(zp, dl_w, dl_b, kn);
    feats_kernel<<<(NB*49152 + 127)/128, 128>>>(zp, fl_w, fl_b, ft);

    // ---- fused triline query + MLP decoder ----
    decode_kernel<<<NB*P3/256, 256>>>(coords, kn, ft, dw1, db1, dw2, db2, out);
}